// round 4
// baseline (speedup 1.0000x reference)
#include <cuda_runtime.h>

// Problem constants (match reference)
#define B_VAL   16384
#define NJ_VAL  14
#define COL_VAL 14
#define NJOINTS (B_VAL * NJ_VAL)                      // 229376
#define H_ELEMS ((long long)B_VAL * NJ_VAL * COL_VAL * COL_VAL)  // 44,957,696
#define H_VEC4  (H_ELEMS / 4)                         // 11,239,424
#define DIVISOR ((double)H_ELEMS / 2.0)               // 22,478,848

// Single-wave persistent grid: 152 SMs * 8 blocks (regs<=32 -> 8 x 256thr fit)
#define NBLOCKS   1216
#define NTHREADS  256
#define TOT_THREADS (NBLOCKS * NTHREADS)              // 311,296

// Distributed accumulator slots (128B apart) + completion counter.
// Reset by the last block so every graph replay starts clean.
#define NSLOTS       32
#define SLOT_STRIDE  16   // doubles (128 bytes)
__device__ double       g_acc[NSLOTS * SLOT_STRIDE];
__device__ unsigned int g_done = 0;

__global__ __launch_bounds__(NTHREADS) void mse2_fused_kernel(
    const float4* __restrict__ h4,
    const float*  __restrict__ h,
    const float*  __restrict__ t,
    const int*    __restrict__ v,
    float*        __restrict__ out) {

    const long long stride = TOT_THREADS;
    long long i = (long long)blockIdx.x * NTHREADS + threadIdx.x;

    float s0 = 0.0f, s1 = 0.0f, s2 = 0.0f, s3 = 0.0f;

    // ---- Persistent streaming loop: 4 independent LDG.128 per iteration ----
    const long long main_limit = H_VEC4 - 3 * stride;
    for (; i < main_limit; i += 4 * stride) {
        float4 a = __ldcs(&h4[i]);
        float4 b = __ldcs(&h4[i +     stride]);
        float4 c = __ldcs(&h4[i + 2 * stride]);
        float4 d = __ldcs(&h4[i + 3 * stride]);
        s0 += a.x * a.x + a.y * a.y + a.z * a.z + a.w * a.w;
        s1 += b.x * b.x + b.y * b.y + b.z * b.z + b.w * b.w;
        s2 += c.x * c.x + c.y * c.y + c.z * c.z + c.w * c.w;
        s3 += d.x * d.x + d.y * d.y + d.z * d.z + d.w * d.w;
    }
    // Tail (at most 3 loads per thread)
    for (; i < H_VEC4; i += stride) {
        float4 a = __ldcs(&h4[i]);
        s0 += a.x * a.x + a.y * a.y + a.z * a.z + a.w * a.w;
    }
    float sum = (s0 + s1) + (s2 + s3);

    // ---- Joint correction: visible one-hot cell -> (h-1)^2 - h^2 = 1 - 2h ----
    int gid = blockIdx.x * NTHREADS + threadIdx.x;
    if (gid < NJOINTS) {
        if (v[gid] == 1) {
            float tx = t[2 * gid + 0];
            float ty = t[2 * gid + 1];
            int xi = (int)(tx * (float)COL_VAL);   // trunc toward zero, t >= 0
            int yi = (int)(ty * (float)COL_VAL);
            xi = min(max(xi, 0), COL_VAL - 1);
            yi = min(max(yi, 0), COL_VAL - 1);
            float hv = h[(long long)gid * (COL_VAL * COL_VAL) + xi * COL_VAL + yi];
            sum += 1.0f - 2.0f * hv;
        }
    }

    // ---- Warp reduce ----
    #pragma unroll
    for (int off = 16; off > 0; off >>= 1)
        sum += __shfl_down_sync(0xFFFFFFFFu, sum, off);

    // ---- Block reduce ----
    __shared__ float warp_sums[NTHREADS / 32];
    int lane = threadIdx.x & 31;
    int wid  = threadIdx.x >> 5;
    if (lane == 0) warp_sums[wid] = sum;
    __syncthreads();

    __shared__ bool is_last;
    if (wid == 0) {
        float s = (lane < (NTHREADS >> 5)) ? warp_sums[lane] : 0.0f;
        #pragma unroll
        for (int off = 4; off > 0; off >>= 1)
            s += __shfl_down_sync(0xFFFFFFFFu, s, off);
        if (lane == 0) {
            int slot = (blockIdx.x & (NSLOTS - 1)) * SLOT_STRIDE;
            atomicAdd(&g_acc[slot], (double)s);
            __threadfence();
            unsigned int prev = atomicAdd(&g_done, 1u);
            is_last = (prev == (unsigned int)(gridDim.x - 1));
        }
    }
    __syncthreads();

    // ---- Last block finalizes: sum slots, write output, reset state ----
    if (is_last && threadIdx.x == 0) {
        double total = 0.0;
        #pragma unroll
        for (int j = 0; j < NSLOTS; j++) {
            total += g_acc[j * SLOT_STRIDE];
            g_acc[j * SLOT_STRIDE] = 0.0;
        }
        out[0] = (float)(total / DIVISOR);
        __threadfence();
        g_done = 0;
    }
}

extern "C" void kernel_launch(void* const* d_in, const int* in_sizes, int n_in,
                              void* d_out, int out_size) {
    // metadata order: o (unused), h, t, v
    const float* h = (const float*)d_in[1];
    const float* t = (const float*)d_in[2];
    const int*   v = (const int*)d_in[3];
    float* out = (float*)d_out;

    mse2_fused_kernel<<<NBLOCKS, NTHREADS>>>((const float4*)h, h, t, v, out);
}

// round 5
// speedup vs baseline: 1.0183x; 1.0183x over previous
#include <cuda_runtime.h>

// Problem constants (match reference)
#define B_VAL   16384
#define NJ_VAL  14
#define COL_VAL 14
#define NJOINTS (B_VAL * NJ_VAL)                      // 229376
#define H_ELEMS (B_VAL * NJ_VAL * COL_VAL * COL_VAL)  // 44,957,696 (fits int)
#define H_VEC4  (H_ELEMS / 4)                         // 11,239,424
#define DIVISOR ((double)H_ELEMS / 2.0)               // 22,478,848

// Single-wave persistent grid: 152 SMs * 8 blocks. launch_bounds(256, 8)
// forces regs <= 32 so all 1216 blocks are co-resident (one true wave).
#define NBLOCKS   1216
#define NTHREADS  256
#define TOT_THREADS (NBLOCKS * NTHREADS)              // 311,296

// Distributed accumulator slots (128B apart) + completion counter.
// Reset by the last block so every graph replay starts clean.
#define NSLOTS       32
#define SLOT_STRIDE  16   // doubles (128 bytes)
__device__ double       g_acc[NSLOTS * SLOT_STRIDE];
__device__ unsigned int g_done = 0;

__global__ __launch_bounds__(NTHREADS, 8) void mse2_fused_kernel(
    const float4* __restrict__ h4,
    const float*  __restrict__ h,
    const float*  __restrict__ t,
    const int*    __restrict__ v,
    float*        __restrict__ out) {

    const int stride = TOT_THREADS;
    int i = blockIdx.x * NTHREADS + threadIdx.x;

    float s0 = 0.0f, s1 = 0.0f, s2 = 0.0f, s3 = 0.0f;

    // ---- Persistent streaming loop: 4 independent LDG.128 per iteration ----
    // H_VEC4 / TOT_THREADS = 36.1 -> 9 full iterations for most threads.
    const int main_limit = H_VEC4 - 3 * stride;
    for (; i < main_limit; i += 4 * stride) {
        float4 a = __ldcs(&h4[i]);
        float4 b = __ldcs(&h4[i +     stride]);
        float4 c = __ldcs(&h4[i + 2 * stride]);
        float4 d = __ldcs(&h4[i + 3 * stride]);
        s0 += a.x * a.x + a.y * a.y + a.z * a.z + a.w * a.w;
        s1 += b.x * b.x + b.y * b.y + b.z * b.z + b.w * b.w;
        s2 += c.x * c.x + c.y * c.y + c.z * c.z + c.w * c.w;
        s3 += d.x * d.x + d.y * d.y + d.z * d.z + d.w * d.w;
    }
    // Tail (at most 3 loads per thread)
    for (; i < H_VEC4; i += stride) {
        float4 a = __ldcs(&h4[i]);
        s0 += a.x * a.x + a.y * a.y + a.z * a.z + a.w * a.w;
    }
    float sum = (s0 + s1) + (s2 + s3);

    // ---- Joint correction: visible one-hot cell -> (h-1)^2 - h^2 = 1 - 2h ----
    int gid = blockIdx.x * NTHREADS + threadIdx.x;
    if (gid < NJOINTS) {
        if (v[gid] == 1) {
            float tx = t[2 * gid + 0];
            float ty = t[2 * gid + 1];
            int xi = (int)(tx * (float)COL_VAL);   // trunc toward zero, t >= 0
            int yi = (int)(ty * (float)COL_VAL);
            xi = min(max(xi, 0), COL_VAL - 1);
            yi = min(max(yi, 0), COL_VAL - 1);
            float hv = h[gid * (COL_VAL * COL_VAL) + xi * COL_VAL + yi];
            sum += 1.0f - 2.0f * hv;
        }
    }

    // ---- Warp reduce ----
    #pragma unroll
    for (int off = 16; off > 0; off >>= 1)
        sum += __shfl_down_sync(0xFFFFFFFFu, sum, off);

    // ---- Block reduce ----
    __shared__ float warp_sums[NTHREADS / 32];
    int lane = threadIdx.x & 31;
    int wid  = threadIdx.x >> 5;
    if (lane == 0) warp_sums[wid] = sum;
    __syncthreads();

    __shared__ bool is_last;
    if (wid == 0) {
        float s = (lane < (NTHREADS >> 5)) ? warp_sums[lane] : 0.0f;
        #pragma unroll
        for (int off = 4; off > 0; off >>= 1)
            s += __shfl_down_sync(0xFFFFFFFFu, s, off);
        if (lane == 0) {
            int slot = (blockIdx.x & (NSLOTS - 1)) * SLOT_STRIDE;
            atomicAdd(&g_acc[slot], (double)s);
            __threadfence();
            unsigned int prev = atomicAdd(&g_done, 1u);
            is_last = (prev == (unsigned int)(gridDim.x - 1));
        }
    }
    __syncthreads();

    // ---- Last block finalizes: sum slots, write output, reset state ----
    if (is_last && threadIdx.x == 0) {
        double total = 0.0;
        #pragma unroll
        for (int j = 0; j < NSLOTS; j++) {
            total += g_acc[j * SLOT_STRIDE];
            g_acc[j * SLOT_STRIDE] = 0.0;
        }
        out[0] = (float)(total / DIVISOR);
        __threadfence();
        g_done = 0;
    }
}

extern "C" void kernel_launch(void* const* d_in, const int* in_sizes, int n_in,
                              void* d_out, int out_size) {
    // metadata order: o (unused), h, t, v
    const float* h = (const float*)d_in[1];
    const float* t = (const float*)d_in[2];
    const int*   v = (const int*)d_in[3];
    float* out = (float*)d_out;

    mse2_fused_kernel<<<NBLOCKS, NTHREADS>>>((const float4*)h, h, t, v, out);
}